// round 6
// baseline (speedup 1.0000x reference)
#include <cuda_runtime.h>
#include <cuda_bf16.h>
#include <cstdint>

// ---------------------------------------------------------------------------
// Problem constants
// ---------------------------------------------------------------------------
constexpr int B_   = 8192;
constexpr int T_   = 658;
constexpr int I_   = 7;
constexpr int D1_  = 1024;
constexpr int D2_  = 512;
constexpr int D3_  = 128;
constexpr int XWT  = 688;            // T_ padded for scan prefetch overrun
constexpr int TPAD = 672;            // T_ padded to multiple of 32 (GEMM1 K)

// ---------------------------------------------------------------------------
// Scratch (device globals zero-init; padded regions either rewritten or 0)
// ---------------------------------------------------------------------------
__device__ float          g_xw [(size_t)XWT * B_];     // [T,B] fp32 (rows >= T_ stay 0)
__device__ __nv_bfloat16  g_ath[(size_t)B_ * TPAD];    // hs^T hi  [B,TPAD]
__device__ __nv_bfloat16  g_atl[(size_t)B_ * TPAD];    // hs^T lo

__device__ __nv_bfloat16  g_w1h[(size_t)D1_ * TPAD], g_w1l[(size_t)D1_ * TPAD];
__device__ __nv_bfloat16  g_w2h[(size_t)D2_ * D1_ ], g_w2l[(size_t)D2_ * D1_ ];
__device__ __nv_bfloat16  g_w3h[(size_t)D3_ * D2_ ], g_w3l[(size_t)D3_ * D2_ ];
__device__ __nv_bfloat16  g_w4h[(size_t)T_  * D3_ ], g_w4l[(size_t)T_  * D3_ ];

__device__ __nv_bfloat16  g_y1h[(size_t)B_ * D1_], g_y1l[(size_t)B_ * D1_];
__device__ __nv_bfloat16  g_y2h[(size_t)B_ * D2_], g_y2l[(size_t)B_ * D2_];
__device__ __nv_bfloat16  g_y3h[(size_t)B_ * D3_], g_y3l[(size_t)B_ * D3_];

// ---------------------------------------------------------------------------
// PTX helpers (base-target ISA only: ldmatrix / mma.sync / cp.async)
// ---------------------------------------------------------------------------
__device__ __forceinline__ uint32_t smem_u32(const void* p) {
    uint32_t a;
    asm("{ .reg .u64 t; cvta.to.shared.u64 t, %1; cvt.u32.u64 %0, t; }" : "=r"(a) : "l"(p));
    return a;
}

__device__ __forceinline__ void cp16(uint32_t dst, const void* src, int srcsize) {
    asm volatile("cp.async.cg.shared.global [%0], [%1], 16, %2;"
                 :: "r"(dst), "l"(src), "r"(srcsize));
}
#define CP_COMMIT() asm volatile("cp.async.commit_group;" ::: "memory")
#define CP_WAIT(n)  asm volatile("cp.async.wait_group %0;" :: "n"(n) : "memory")

#define LDSM4(r, a)                                                             \
    asm volatile("ldmatrix.sync.aligned.m8n8.x4.shared.b16 {%0,%1,%2,%3}, [%4];"\
                 : "=r"((r)[0]), "=r"((r)[1]), "=r"((r)[2]), "=r"((r)[3])       \
                 : "r"(a))

__device__ __forceinline__ void mma16816(float* d, const uint32_t* a,
                                         uint32_t b0, uint32_t b1) {
    asm volatile("mma.sync.aligned.m16n8k16.row.col.f32.bf16.bf16.f32 "
                 "{%0,%1,%2,%3}, {%4,%5,%6,%7}, {%8,%9}, {%0,%1,%2,%3};"
                 : "+f"(d[0]), "+f"(d[1]), "+f"(d[2]), "+f"(d[3])
                 : "r"(a[0]), "r"(a[1]), "r"(a[2]), "r"(a[3]), "r"(b0), "r"(b1));
}

// ---------------------------------------------------------------------------
// Stage 1: xw[t,b] = dot(x[b,t,:], W_ih) + b_ih + b_hh   ([T,B] fp32)
// ---------------------------------------------------------------------------
__global__ void proj_kernel(const float* __restrict__ x,
                            const float* __restrict__ W_ih,
                            const float* __restrict__ b_ih,
                            const float* __restrict__ b_hh) {
    __shared__ float xs[32][225];
    const int t0 = blockIdx.x * 32;
    const int b0 = blockIdx.y * 32;
    const int tid = threadIdx.x;
    const int tlim = min(32, T_ - t0);
    const int nfl = tlim * I_;

    for (int i = tid; i < 32 * 224; i += 256) {
        int bl = i / 224;
        int off = i - bl * 224;
        float v = 0.f;
        if (off < nfl) v = x[((size_t)(b0 + bl) * T_ + t0) * I_ + off];
        xs[bl][off] = v;
    }
    __syncthreads();

    float w[7];
#pragma unroll
    for (int j = 0; j < 7; ++j) w[j] = W_ih[j];
    const float bias = b_ih[0] + b_hh[0];

    for (int i = tid; i < 1024; i += 256) {
        int bl = i & 31;
        int tl = i >> 5;
        if (tl < tlim) {
            const float* row = &xs[bl][tl * 7];
            float s = bias;
#pragma unroll
            for (int j = 0; j < 7; ++j) s = fmaf(row[j], w[j], s);
            g_xw[(size_t)(t0 + tl) * B_ + (b0 + bl)] = s;
        }
    }
}

// ---------------------------------------------------------------------------
// Stage 2: scalar tanh recurrence -> g_ath/g_atl [B,TPAD] bf16 hi/lo direct.
//   32-step chunks staged in smem (packed hi|lo uint32), flushed with paired
//   32-bit stores. Pad steps t in [T_,TPAD) produce junk h, harmless: those
//   A-columns multiply zero-padded weight columns. Hidden = h at t == T_-1.
// ---------------------------------------------------------------------------
__device__ __forceinline__ float tanh_fast(float xv) {
    float ax = fabsf(xv);
    float e = __expf(-2.0f * ax);
    float r = __fdividef(1.0f - e, 1.0f + e);
    return copysignf(r, xv);
}

__device__ __forceinline__ uint32_t pack_hilo(float v) {
    __nv_bfloat16 h = __float2bfloat16(v);
    __nv_bfloat16 l = __float2bfloat16(v - __bfloat162float(h));
    return (uint32_t)__bfloat16_as_ushort(h) | ((uint32_t)__bfloat16_as_ushort(l) << 16);
}

__global__ void __launch_bounds__(256)
scan_kernel(const float* __restrict__ h0,
            const float* __restrict__ W_hh,
            float* __restrict__ hid) {
    __shared__ uint32_t sh[256][33];   // row stride 33 words: conflict-free writes
    const int tid = threadIdx.x;
    const int b0 = blockIdx.x * 256;
    const int b  = b0 + tid;

    const float whh = W_hh[0];
    const float* xp = g_xw + b;
    float h = h0[b];
    float hT = h;

    float bufA[16], bufB[16];
#pragma unroll
    for (int j = 0; j < 16; ++j) bufA[j] = xp[(size_t)j * B_];

    for (int tc = 0; tc < TPAD; tc += 32) {
#pragma unroll
        for (int j = 0; j < 16; ++j) bufB[j] = xp[(size_t)(tc + 16 + j) * B_];
#pragma unroll
        for (int j = 0; j < 16; ++j) {
            h = tanh_fast(fmaf(h, whh, bufA[j]));
            sh[tid][j] = pack_hilo(h);
            if (tc + j == T_ - 1) hT = h;
        }
#pragma unroll
        for (int j = 0; j < 16; ++j) bufA[j] = xp[(size_t)(tc + 32 + j) * B_];  // max 687 < XWT
#pragma unroll
        for (int j = 0; j < 16; ++j) {
            h = tanh_fast(fmaf(h, whh, bufB[j]));
            sh[tid][16 + j] = pack_hilo(h);
            if (tc + 16 + j == T_ - 1) hT = h;
        }
        __syncthreads();
        // paired flush: thread handles 2 adjacent t -> one STG.32 per array
#pragma unroll
        for (int it = 0; it < 16; ++it) {
            int lin = it * 256 + tid;        // 4096 pairs
            int r = lin >> 4;                // b-row 0..255
            int p = lin & 15;                // pair index
            uint32_t v0 = sh[r][2 * p];
            uint32_t v1 = sh[r][2 * p + 1];
            size_t o = (size_t)(b0 + r) * TPAD + tc + 2 * p;
            *(uint32_t*)(g_ath + o) = (v0 & 0xffffu) | (v1 << 16);
            *(uint32_t*)(g_atl + o) = (v0 >> 16) | (v1 & 0xffff0000u);
        }
        __syncthreads();
    }
    if (hid) hid[b] = hT;
}

// ---------------------------------------------------------------------------
// Weight conversion, all 4 layers in one launch (grid.y = layer)
// ---------------------------------------------------------------------------
__device__ __forceinline__ void cvt_seg(const float* __restrict__ src,
                                        __nv_bfloat16* __restrict__ hi,
                                        __nv_bfloat16* __restrict__ lo,
                                        int R, int K, int Kp, int i) {
    if (i < R * K) {
        int r = i / K, k = i - r * K;
        float v = src[i];
        __nv_bfloat16 h = __float2bfloat16(v);
        hi[(size_t)r * Kp + k] = h;
        lo[(size_t)r * Kp + k] = __float2bfloat16(v - __bfloat162float(h));
    }
}

__global__ void cvt_all(const float* __restrict__ w1, const float* __restrict__ w2,
                        const float* __restrict__ w3, const float* __restrict__ w4) {
    int i = blockIdx.x * 256 + threadIdx.x;
    switch (blockIdx.y) {
        case 0: cvt_seg(w1, g_w1h, g_w1l, D1_, T_,  TPAD, i); break;
        case 1: cvt_seg(w2, g_w2h, g_w2l, D2_, D1_, D1_,  i); break;
        case 2: cvt_seg(w3, g_w3h, g_w3l, D3_, D2_, D2_,  i); break;
        case 3: cvt_seg(w4, g_w4h, g_w4l, T_,  D3_, D3_,  i); break;
    }
}

// ---------------------------------------------------------------------------
// mma.sync GEMM: C[M,N] = act(A * B^T + bias), 3-term bf16 hi/lo split.
//   A: [M,K] bf16 hi/lo row-major.  B: [N,K] bf16 hi/lo K-major.
//   CTA 128x128, BK=32, warp tile 32x64 (4x2 warps).
//   3-stage cp.async pipeline, ONE barrier per chunk, loads 2 chunks ahead.
// ---------------------------------------------------------------------------
constexpr int PITCH = 80;
constexpr int MATSZ = 128 * PITCH;          // 10240
constexpr int STAGE = 4 * MATSZ;            // 40960
constexpr int NSTG  = 3;
constexpr int GEMM_SMEM = NSTG * STAGE;     // 122880

__device__ __forceinline__ void load_stage(
        uint32_t sbase, int slot, int k0, int tid,
        const __nv_bfloat16* Ah, const __nv_bfloat16* Al,
        const __nv_bfloat16* Bh, const __nv_bfloat16* Bl,
        int K, int N, int bm, int bn) {
#pragma unroll
    for (int it = 0; it < 8; ++it) {
        int i = tid + it * 256;
        int mat = i >> 9;          // 0:Ah 1:Al 2:Bh 3:Bl
        int row = (i >> 2) & 127;
        int seg = i & 3;
        uint32_t dst = sbase + slot * STAGE + mat * MATSZ + row * PITCH + seg * 16;
        const __nv_bfloat16* src;
        int size = 16;
        if (mat < 2) {
            src = (mat == 0 ? Ah : Al) + (size_t)(bm + row) * K + k0 + seg * 8;
        } else {
            const __nv_bfloat16* base = (mat == 2 ? Bh : Bl);
            int n = bn + row;
            if (n < N) {
                src = base + (size_t)n * K + k0 + seg * 8;
            } else {
                src = base + k0 + seg * 8;
                size = 0;
            }
        }
        cp16(dst, src, size);
    }
}

template <bool RELU, bool F32OUT>
__global__ void __launch_bounds__(256)
gemm_mma(const __nv_bfloat16* __restrict__ Ah, const __nv_bfloat16* __restrict__ Al,
         const __nv_bfloat16* __restrict__ Bh, const __nv_bfloat16* __restrict__ Bl,
         const float* __restrict__ bias,
         __nv_bfloat16* __restrict__ Oh, __nv_bfloat16* __restrict__ Ol,
         float* __restrict__ Of,
         int K, int N, int strideO) {
    extern __shared__ char smem[];
    const uint32_t sbase = smem_u32(smem);
    const int tid = threadIdx.x;
    const int lane = tid & 31;
    const int wid = tid >> 5;
    const int wm = wid & 3;         // 4 warps over M
    const int wn = wid >> 2;        // 2 warps over N
    const int bm = blockIdx.x * 128;
    const int bn = blockIdx.y * 128;
    const int nk = K >> 5;

    float acc[2][8][4];
#pragma unroll
    for (int i = 0; i < 2; ++i)
#pragma unroll
        for (int j = 0; j < 8; ++j)
#pragma unroll
            for (int q = 0; q < 4; ++q) acc[i][j][q] = 0.f;

    const uint32_t a_addr = sbase + (wm * 32 + (lane & 15)) * PITCH + (lane >> 4) * 16;
    const uint32_t b_addr = sbase + 2 * MATSZ +
        (wn * 64 + (lane & 7) + ((lane >> 4) * 8)) * PITCH + ((lane >> 3) & 1) * 16;

    // prologue: 2 stages in flight
    load_stage(sbase, 0, 0, tid, Ah, Al, Bh, Bl, K, N, bm, bn);
    CP_COMMIT();
    if (nk > 1) {
        load_stage(sbase, 1, 32, tid, Ah, Al, Bh, Bl, K, N, bm, bn);
        CP_COMMIT();
    }

    for (int kc = 0; kc < nk; ++kc) {
        if (kc + 1 < nk) { CP_WAIT(1); } else { CP_WAIT(0); }
        __syncthreads();                     // stage kc visible; slot (kc+2)%3 free
        if (kc + 2 < nk) {
            load_stage(sbase, (kc + 2) % NSTG, (kc + 2) * 32, tid,
                       Ah, Al, Bh, Bl, K, N, bm, bn);
            CP_COMMIT();
        }

        const uint32_t st = (uint32_t)(kc % NSTG) * STAGE;
#pragma unroll
        for (int kk = 0; kk < 2; ++kk) {
            const uint32_t ko = kk * 32;
            uint32_t aH[2][4], aL[2][4];
#pragma unroll
            for (int mi = 0; mi < 2; ++mi) {
                LDSM4(aH[mi], a_addr + st + mi * (16 * PITCH) + ko);
                LDSM4(aL[mi], a_addr + st + MATSZ + mi * (16 * PITCH) + ko);
            }
            uint32_t bH[4][4], bL[4][4];
#pragma unroll
            for (int np = 0; np < 4; ++np) {
                LDSM4(bH[np], b_addr + st + np * (16 * PITCH) + ko);
                LDSM4(bL[np], b_addr + st + MATSZ + np * (16 * PITCH) + ko);
            }
            // term-major: 16 independent MMAs between accumulator reuses
#pragma unroll
            for (int mi = 0; mi < 2; ++mi)
#pragma unroll
                for (int np = 0; np < 4; ++np) {
                    mma16816(acc[mi][np * 2],     aH[mi], bH[np][0], bH[np][1]);
                    mma16816(acc[mi][np * 2 + 1], aH[mi], bH[np][2], bH[np][3]);
                }
#pragma unroll
            for (int mi = 0; mi < 2; ++mi)
#pragma unroll
                for (int np = 0; np < 4; ++np) {
                    mma16816(acc[mi][np * 2],     aH[mi], bL[np][0], bL[np][1]);
                    mma16816(acc[mi][np * 2 + 1], aH[mi], bL[np][2], bL[np][3]);
                }
#pragma unroll
            for (int mi = 0; mi < 2; ++mi)
#pragma unroll
                for (int np = 0; np < 4; ++np) {
                    mma16816(acc[mi][np * 2],     aL[mi], bH[np][0], bH[np][1]);
                    mma16816(acc[mi][np * 2 + 1], aL[mi], bH[np][2], bH[np][3]);
                }
        }
    }

    // Epilogue
    const int g = lane >> 2, tig = lane & 3;
#pragma unroll
    for (int mi = 0; mi < 2; ++mi) {
#pragma unroll
        for (int np = 0; np < 4; ++np) {
#pragma unroll
            for (int c = 0; c < 2; ++c) {
                int col = bn + wn * 64 + np * 16 + c * 8 + 2 * tig;
                float b0 = 0.f, b1 = 0.f;
                if (col < N) { b0 = bias[col]; b1 = bias[col + 1]; }
                float* a = acc[mi][np * 2 + c];
                int r0 = bm + wm * 32 + mi * 16 + g;
                float v00 = a[0] + b0, v01 = a[1] + b1;
                float v10 = a[2] + b0, v11 = a[3] + b1;
                if (RELU) {
                    v00 = fmaxf(v00, 0.f); v01 = fmaxf(v01, 0.f);
                    v10 = fmaxf(v10, 0.f); v11 = fmaxf(v11, 0.f);
                }
                if (F32OUT) {
                    if (col < N) {
                        *(float2*)(Of + (size_t)r0 * strideO + col) = make_float2(v00, v01);
                        *(float2*)(Of + (size_t)(r0 + 8) * strideO + col) = make_float2(v10, v11);
                    }
                } else {
                    __nv_bfloat16 h00 = __float2bfloat16(v00), h01 = __float2bfloat16(v01);
                    __nv_bfloat16 h10 = __float2bfloat16(v10), h11 = __float2bfloat16(v11);
                    __nv_bfloat16 l00 = __float2bfloat16(v00 - __bfloat162float(h00));
                    __nv_bfloat16 l01 = __float2bfloat16(v01 - __bfloat162float(h01));
                    __nv_bfloat16 l10 = __float2bfloat16(v10 - __bfloat162float(h10));
                    __nv_bfloat16 l11 = __float2bfloat16(v11 - __bfloat162float(h11));
                    uint32_t ph0 = (uint32_t)__bfloat16_as_ushort(h00) | ((uint32_t)__bfloat16_as_ushort(h01) << 16);
                    uint32_t pl0 = (uint32_t)__bfloat16_as_ushort(l00) | ((uint32_t)__bfloat16_as_ushort(l01) << 16);
                    uint32_t ph1 = (uint32_t)__bfloat16_as_ushort(h10) | ((uint32_t)__bfloat16_as_ushort(h11) << 16);
                    uint32_t pl1 = (uint32_t)__bfloat16_as_ushort(l10) | ((uint32_t)__bfloat16_as_ushort(l11) << 16);
                    *(uint32_t*)(Oh + (size_t)r0 * strideO + col) = ph0;
                    *(uint32_t*)(Ol + (size_t)r0 * strideO + col) = pl0;
                    *(uint32_t*)(Oh + (size_t)(r0 + 8) * strideO + col) = ph1;
                    *(uint32_t*)(Ol + (size_t)(r0 + 8) * strideO + col) = pl1;
                }
            }
        }
    }
}

// ---------------------------------------------------------------------------
extern "C" void kernel_launch(void* const* d_in, const int* in_sizes, int n_in,
                              void* d_out, int out_size) {
    const float* x    = (const float*)d_in[0];
    const float* h0   = (const float*)d_in[1];
    const float* W_ih = (const float*)d_in[2];
    const float* W_hh = (const float*)d_in[3];
    const float* b_ih = (const float*)d_in[4];
    const float* b_hh = (const float*)d_in[5];
    const float* w1   = (const float*)d_in[6];
    const float* b1   = (const float*)d_in[7];
    const float* w2   = (const float*)d_in[8];
    const float* b2   = (const float*)d_in[9];
    const float* w3   = (const float*)d_in[10];
    const float* b3   = (const float*)d_in[11];
    const float* w4   = (const float*)d_in[12];
    const float* b4   = (const float*)d_in[13];
    float* out = (float*)d_out;
    float* hid = (out_size >= B_ * T_ + B_) ? out + (size_t)B_ * T_ : nullptr;

    __nv_bfloat16 *ath, *atl, *w1h, *w1l, *w2h, *w2l, *w3h, *w3l, *w4h, *w4l;
    __nv_bfloat16 *y1h, *y1l, *y2h, *y2l, *y3h, *y3l;
    cudaGetSymbolAddress((void**)&ath, g_ath); cudaGetSymbolAddress((void**)&atl, g_atl);
    cudaGetSymbolAddress((void**)&w1h, g_w1h); cudaGetSymbolAddress((void**)&w1l, g_w1l);
    cudaGetSymbolAddress((void**)&w2h, g_w2h); cudaGetSymbolAddress((void**)&w2l, g_w2l);
    cudaGetSymbolAddress((void**)&w3h, g_w3h); cudaGetSymbolAddress((void**)&w3l, g_w3l);
    cudaGetSymbolAddress((void**)&w4h, g_w4h); cudaGetSymbolAddress((void**)&w4l, g_w4l);
    cudaGetSymbolAddress((void**)&y1h, g_y1h); cudaGetSymbolAddress((void**)&y1l, g_y1l);
    cudaGetSymbolAddress((void**)&y2h, g_y2h); cudaGetSymbolAddress((void**)&y2l, g_y2l);
    cudaGetSymbolAddress((void**)&y3h, g_y3h); cudaGetSymbolAddress((void**)&y3l, g_y3l);

    cudaFuncSetAttribute(gemm_mma<true,  false>, cudaFuncAttributeMaxDynamicSharedMemorySize, GEMM_SMEM);
    cudaFuncSetAttribute(gemm_mma<false, true >, cudaFuncAttributeMaxDynamicSharedMemorySize, GEMM_SMEM);

    // Launch order: gemm1 stays at index 3 (ncu capture slot).
    // 1) input projection (fp32, [T,B])
    proj_kernel<<<dim3((T_ + 31) / 32, B_ / 32), 256>>>(x, W_ih, b_ih, b_hh);
    // 2) recurrence -> g_ath/g_atl [B,TPAD] (transpose fused), hidden -> out tail
    scan_kernel<<<B_ / 256, 256>>>(h0, W_hh, hid);
    // 3) all weight conversions in one launch
    cvt_all<<<dim3((D1_ * T_ + 255) / 256, 4), 256>>>(w1, w2, w3, w4);
    // 4) y1 = relu(hsT @ w1^T + b1)   M=8192 N=1024 K=672
    gemm_mma<true, false><<<dim3(B_ / 128, D1_ / 128), 256, GEMM_SMEM>>>(
        ath, atl, w1h, w1l, b1, y1h, y1l, nullptr, TPAD, D1_, D1_);
    // 5) y2 = relu(y1 @ w2^T + b2)    K=1024
    gemm_mma<true, false><<<dim3(B_ / 128, D2_ / 128), 256, GEMM_SMEM>>>(
        y1h, y1l, w2h, w2l, b2, y2h, y2l, nullptr, D1_, D2_, D2_);
    // 6) y3 = relu(y2 @ w3^T + b3)    K=512
    gemm_mma<true, false><<<dim3(B_ / 128, D3_ / 128), 256, GEMM_SMEM>>>(
        y2h, y2l, w3h, w3l, b3, y3h, y3l, nullptr, D2_, D3_, D3_);
    // 7) out = y3 @ w4^T + b4         K=128, N=658 (masked)
    gemm_mma<false, true><<<dim3(B_ / 128, (T_ + 127) / 128), 256, GEMM_SMEM>>>(
        y3h, y3l, w4h, w4l, b4, nullptr, nullptr, out, D3_, T_, T_);
}

// round 7
// speedup vs baseline: 1.1614x; 1.1614x over previous
#include <cuda_runtime.h>
#include <cuda_bf16.h>
#include <cstdint>

// ---------------------------------------------------------------------------
// Problem constants
// ---------------------------------------------------------------------------
constexpr int B_   = 8192;
constexpr int T_   = 658;
constexpr int I_   = 7;
constexpr int D1_  = 1024;
constexpr int D2_  = 512;
constexpr int D3_  = 128;
constexpr int XWT  = 688;            // T_ padded for scan prefetch overrun
constexpr int TPAD = 672;            // T_ padded to multiple of 32 (GEMM1 K)

// ---------------------------------------------------------------------------
// Scratch (device globals zero-init; padded regions either rewritten or 0)
// ---------------------------------------------------------------------------
__device__ float          g_xw [(size_t)XWT * B_];     // [T,B] fp32 (rows >= T_ stay 0)
__device__ __nv_bfloat16  g_ath[(size_t)B_ * TPAD];    // hs^T hi  [B,TPAD]
__device__ __nv_bfloat16  g_atl[(size_t)B_ * TPAD];    // hs^T lo

__device__ __nv_bfloat16  g_w1h[(size_t)D1_ * TPAD], g_w1l[(size_t)D1_ * TPAD];
__device__ __nv_bfloat16  g_w2h[(size_t)D2_ * D1_ ], g_w2l[(size_t)D2_ * D1_ ];
__device__ __nv_bfloat16  g_w3h[(size_t)D3_ * D2_ ], g_w3l[(size_t)D3_ * D2_ ];
__device__ __nv_bfloat16  g_w4h[(size_t)T_  * D3_ ], g_w4l[(size_t)T_  * D3_ ];

__device__ __nv_bfloat16  g_y1h[(size_t)B_ * D1_], g_y1l[(size_t)B_ * D1_];
__device__ __nv_bfloat16  g_y2h[(size_t)B_ * D2_], g_y2l[(size_t)B_ * D2_];
__device__ __nv_bfloat16  g_y3h[(size_t)B_ * D3_], g_y3l[(size_t)B_ * D3_];

// ---------------------------------------------------------------------------
// PTX helpers (base-target ISA only: ldmatrix / mma.sync / cp.async)
// ---------------------------------------------------------------------------
__device__ __forceinline__ uint32_t smem_u32(const void* p) {
    uint32_t a;
    asm("{ .reg .u64 t; cvta.to.shared.u64 t, %1; cvt.u32.u64 %0, t; }" : "=r"(a) : "l"(p));
    return a;
}

__device__ __forceinline__ void cp16(uint32_t dst, const void* src, int srcsize) {
    asm volatile("cp.async.cg.shared.global [%0], [%1], 16, %2;"
                 :: "r"(dst), "l"(src), "r"(srcsize));
}
#define CP_COMMIT() asm volatile("cp.async.commit_group;" ::: "memory")
#define CP_WAIT(n)  asm volatile("cp.async.wait_group %0;" :: "n"(n) : "memory")

#define LDSM4(r, a)                                                             \
    asm volatile("ldmatrix.sync.aligned.m8n8.x4.shared.b16 {%0,%1,%2,%3}, [%4];"\
                 : "=r"((r)[0]), "=r"((r)[1]), "=r"((r)[2]), "=r"((r)[3])       \
                 : "r"(a))

__device__ __forceinline__ void mma16816(float* d, const uint32_t* a,
                                         uint32_t b0, uint32_t b1) {
    asm volatile("mma.sync.aligned.m16n8k16.row.col.f32.bf16.bf16.f32 "
                 "{%0,%1,%2,%3}, {%4,%5,%6,%7}, {%8,%9}, {%0,%1,%2,%3};"
                 : "+f"(d[0]), "+f"(d[1]), "+f"(d[2]), "+f"(d[3])
                 : "r"(a[0]), "r"(a[1]), "r"(a[2]), "r"(a[3]), "r"(b0), "r"(b1));
}

// ---------------------------------------------------------------------------
// Stage 1: xw[t,b] = dot(x[b,t,:], W_ih) + b_ih + b_hh   ([T,B] fp32)
// ---------------------------------------------------------------------------
__global__ void proj_kernel(const float* __restrict__ x,
                            const float* __restrict__ W_ih,
                            const float* __restrict__ b_ih,
                            const float* __restrict__ b_hh) {
    __shared__ float xs[32][225];
    const int t0 = blockIdx.x * 32;
    const int b0 = blockIdx.y * 32;
    const int tid = threadIdx.x;
    const int tlim = min(32, T_ - t0);
    const int nfl = tlim * I_;

    for (int i = tid; i < 32 * 224; i += 256) {
        int bl = i / 224;
        int off = i - bl * 224;
        float v = 0.f;
        if (off < nfl) v = x[((size_t)(b0 + bl) * T_ + t0) * I_ + off];
        xs[bl][off] = v;
    }
    __syncthreads();

    float w[7];
#pragma unroll
    for (int j = 0; j < 7; ++j) w[j] = W_ih[j];
    const float bias = b_ih[0] + b_hh[0];

    for (int i = tid; i < 1024; i += 256) {
        int bl = i & 31;
        int tl = i >> 5;
        if (tl < tlim) {
            const float* row = &xs[bl][tl * 7];
            float s = bias;
#pragma unroll
            for (int j = 0; j < 7; ++j) s = fmaf(row[j], w[j], s);
            g_xw[(size_t)(t0 + tl) * B_ + (b0 + bl)] = s;
        }
    }
}

// ---------------------------------------------------------------------------
// Stage 2: scalar tanh recurrence -> g_ath/g_atl [B,TPAD] bf16 hi/lo direct.
// ---------------------------------------------------------------------------
__device__ __forceinline__ float tanh_fast(float xv) {
    float ax = fabsf(xv);
    float e = __expf(-2.0f * ax);
    float r = __fdividef(1.0f - e, 1.0f + e);
    return copysignf(r, xv);
}

__device__ __forceinline__ uint32_t pack_hilo(float v) {
    __nv_bfloat16 h = __float2bfloat16(v);
    __nv_bfloat16 l = __float2bfloat16(v - __bfloat162float(h));
    return (uint32_t)__bfloat16_as_ushort(h) | ((uint32_t)__bfloat16_as_ushort(l) << 16);
}

__global__ void __launch_bounds__(256)
scan_kernel(const float* __restrict__ h0,
            const float* __restrict__ W_hh,
            float* __restrict__ hid) {
    __shared__ uint32_t sh[256][33];
    const int tid = threadIdx.x;
    const int b0 = blockIdx.x * 256;
    const int b  = b0 + tid;

    const float whh = W_hh[0];
    const float* xp = g_xw + b;
    float h = h0[b];
    float hT = h;

    float bufA[16], bufB[16];
#pragma unroll
    for (int j = 0; j < 16; ++j) bufA[j] = xp[(size_t)j * B_];

    for (int tc = 0; tc < TPAD; tc += 32) {
#pragma unroll
        for (int j = 0; j < 16; ++j) bufB[j] = xp[(size_t)(tc + 16 + j) * B_];
#pragma unroll
        for (int j = 0; j < 16; ++j) {
            h = tanh_fast(fmaf(h, whh, bufA[j]));
            sh[tid][j] = pack_hilo(h);
            if (tc + j == T_ - 1) hT = h;
        }
#pragma unroll
        for (int j = 0; j < 16; ++j) bufA[j] = xp[(size_t)(tc + 32 + j) * B_];  // max 687 < XWT
#pragma unroll
        for (int j = 0; j < 16; ++j) {
            h = tanh_fast(fmaf(h, whh, bufB[j]));
            sh[tid][16 + j] = pack_hilo(h);
            if (tc + 16 + j == T_ - 1) hT = h;
        }
        __syncthreads();
#pragma unroll
        for (int it = 0; it < 16; ++it) {
            int lin = it * 256 + tid;
            int r = lin >> 4;
            int p = lin & 15;
            uint32_t v0 = sh[r][2 * p];
            uint32_t v1 = sh[r][2 * p + 1];
            size_t o = (size_t)(b0 + r) * TPAD + tc + 2 * p;
            *(uint32_t*)(g_ath + o) = (v0 & 0xffffu) | (v1 << 16);
            *(uint32_t*)(g_atl + o) = (v0 >> 16) | (v1 & 0xffff0000u);
        }
        __syncthreads();
    }
    if (hid) hid[b] = hT;
}

// ---------------------------------------------------------------------------
// Weight conversion, all 4 layers in one launch (grid.y = layer)
// ---------------------------------------------------------------------------
__device__ __forceinline__ void cvt_seg(const float* __restrict__ src,
                                        __nv_bfloat16* __restrict__ hi,
                                        __nv_bfloat16* __restrict__ lo,
                                        int R, int K, int Kp, int i) {
    if (i < R * K) {
        int r = i / K, k = i - r * K;
        float v = src[i];
        __nv_bfloat16 h = __float2bfloat16(v);
        hi[(size_t)r * Kp + k] = h;
        lo[(size_t)r * Kp + k] = __float2bfloat16(v - __bfloat162float(h));
    }
}

__global__ void cvt_all(const float* __restrict__ w1, const float* __restrict__ w2,
                        const float* __restrict__ w3, const float* __restrict__ w4) {
    int i = blockIdx.x * 256 + threadIdx.x;
    switch (blockIdx.y) {
        case 0: cvt_seg(w1, g_w1h, g_w1l, D1_, T_,  TPAD, i); break;
        case 1: cvt_seg(w2, g_w2h, g_w2l, D2_, D1_, D1_,  i); break;
        case 2: cvt_seg(w3, g_w3h, g_w3l, D3_, D2_, D2_,  i); break;
        case 3: cvt_seg(w4, g_w4h, g_w4l, T_,  D3_, D3_,  i); break;
    }
}

// ---------------------------------------------------------------------------
// mma.sync GEMM: C[M,N] = act(A * B^T + bias), 3-term bf16 hi/lo split.
//   CTA tile 128x128, BK=32, 4 warps (2x2), warp tile 64x64 (halves smem
//   read redundancy vs 8x 32x64: 64KB/chunk vs 96KB -> tensor-bound).
//   2-stage cp.async pipeline, 80KB smem -> 2 CTAs/SM, no reg cap.
// ---------------------------------------------------------------------------
constexpr int PITCH = 80;
constexpr int MATSZ = 128 * PITCH;        // 10240
constexpr int STAGE = 4 * MATSZ;          // 40960
constexpr int GEMM_SMEM = 2 * STAGE;      // 81920
constexpr int GTHREADS = 128;

__device__ __forceinline__ void load_stage(
        uint32_t sbase, int slot, int k0, int tid,
        const __nv_bfloat16* Ah, const __nv_bfloat16* Al,
        const __nv_bfloat16* Bh, const __nv_bfloat16* Bl,
        int K, int N, int bm, int bn) {
#pragma unroll
    for (int it = 0; it < 16; ++it) {
        int i = tid + it * GTHREADS;
        int mat = i >> 9;          // 0:Ah 1:Al 2:Bh 3:Bl
        int row = (i >> 2) & 127;
        int seg = i & 3;
        uint32_t dst = sbase + slot * STAGE + mat * MATSZ + row * PITCH + seg * 16;
        const __nv_bfloat16* src;
        int size = 16;
        if (mat < 2) {
            src = (mat == 0 ? Ah : Al) + (size_t)(bm + row) * K + k0 + seg * 8;
        } else {
            const __nv_bfloat16* base = (mat == 2 ? Bh : Bl);
            int n = bn + row;
            if (n < N) {
                src = base + (size_t)n * K + k0 + seg * 8;
            } else {
                src = base + k0 + seg * 8;
                size = 0;
            }
        }
        cp16(dst, src, size);
    }
}

template <bool RELU, bool F32OUT>
__global__ void __launch_bounds__(GTHREADS)
gemm_mma(const __nv_bfloat16* __restrict__ Ah, const __nv_bfloat16* __restrict__ Al,
         const __nv_bfloat16* __restrict__ Bh, const __nv_bfloat16* __restrict__ Bl,
         const float* __restrict__ bias,
         __nv_bfloat16* __restrict__ Oh, __nv_bfloat16* __restrict__ Ol,
         float* __restrict__ Of,
         int K, int N, int strideO) {
    extern __shared__ char smem[];
    const uint32_t sbase = smem_u32(smem);
    const int tid = threadIdx.x;
    const int lane = tid & 31;
    const int wid = tid >> 5;       // 0..3
    const int wm = wid & 1;         // 2 warps over M (64 rows each)
    const int wn = wid >> 1;        // 2 warps over N (64 cols each)
    const int bm = blockIdx.x * 128;
    const int bn = blockIdx.y * 128;
    const int nk = K >> 5;

    float acc[4][8][4];             // mi(4 x m16) x (np*2+c)(8 x n8) x 4
#pragma unroll
    for (int i = 0; i < 4; ++i)
#pragma unroll
        for (int j = 0; j < 8; ++j)
#pragma unroll
            for (int q = 0; q < 4; ++q) acc[i][j][q] = 0.f;

    const uint32_t a_addr = sbase + (wm * 64 + (lane & 15)) * PITCH + (lane >> 4) * 16;
    const uint32_t b_addr = sbase + 2 * MATSZ +
        (wn * 64 + (lane & 7) + ((lane >> 4) * 8)) * PITCH + ((lane >> 3) & 1) * 16;

    load_stage(sbase, 0, 0, tid, Ah, Al, Bh, Bl, K, N, bm, bn);
    CP_COMMIT();

    for (int kc = 0; kc < nk; ++kc) {
        __syncthreads();            // all warps done reading buffer about to refill
        if (kc + 1 < nk) {
            load_stage(sbase, (kc + 1) & 1, (kc + 1) * 32, tid, Ah, Al, Bh, Bl, K, N, bm, bn);
            CP_COMMIT();
            CP_WAIT(1);
        } else {
            CP_WAIT(0);
        }
        __syncthreads();

        const uint32_t st = ((kc & 1) ? STAGE : 0);
#pragma unroll
        for (int kk = 0; kk < 2; ++kk) {
            const uint32_t ko = kk * 32;
            uint32_t aH[4][4], aL[4][4];
#pragma unroll
            for (int mi = 0; mi < 4; ++mi) {
                LDSM4(aH[mi], a_addr + st + mi * (16 * PITCH) + ko);
                LDSM4(aL[mi], a_addr + st + MATSZ + mi * (16 * PITCH) + ko);
            }
            uint32_t bH[4][4], bL[4][4];
#pragma unroll
            for (int np = 0; np < 4; ++np) {
                LDSM4(bH[np], b_addr + st + np * (16 * PITCH) + ko);
                LDSM4(bL[np], b_addr + st + MATSZ + np * (16 * PITCH) + ko);
            }
            // term-major: 32 independent MMAs between accumulator reuses
#pragma unroll
            for (int mi = 0; mi < 4; ++mi)
#pragma unroll
                for (int np = 0; np < 4; ++np) {
                    mma16816(acc[mi][np * 2],     aH[mi], bH[np][0], bH[np][1]);
                    mma16816(acc[mi][np * 2 + 1], aH[mi], bH[np][2], bH[np][3]);
                }
#pragma unroll
            for (int mi = 0; mi < 4; ++mi)
#pragma unroll
                for (int np = 0; np < 4; ++np) {
                    mma16816(acc[mi][np * 2],     aH[mi], bL[np][0], bL[np][1]);
                    mma16816(acc[mi][np * 2 + 1], aH[mi], bL[np][2], bL[np][3]);
                }
#pragma unroll
            for (int mi = 0; mi < 4; ++mi)
#pragma unroll
                for (int np = 0; np < 4; ++np) {
                    mma16816(acc[mi][np * 2],     aL[mi], bH[np][0], bH[np][1]);
                    mma16816(acc[mi][np * 2 + 1], aL[mi], bH[np][2], bH[np][3]);
                }
        }
    }

    // Epilogue
    const int g = lane >> 2, tig = lane & 3;
#pragma unroll
    for (int mi = 0; mi < 4; ++mi) {
#pragma unroll
        for (int np = 0; np < 4; ++np) {
#pragma unroll
            for (int c = 0; c < 2; ++c) {
                int col = bn + wn * 64 + np * 16 + c * 8 + 2 * tig;
                float b0 = 0.f, b1 = 0.f;
                if (col < N) { b0 = bias[col]; b1 = bias[col + 1]; }
                float* a = acc[mi][np * 2 + c];
                int r0 = bm + wm * 64 + mi * 16 + g;
                float v00 = a[0] + b0, v01 = a[1] + b1;
                float v10 = a[2] + b0, v11 = a[3] + b1;
                if (RELU) {
                    v00 = fmaxf(v00, 0.f); v01 = fmaxf(v01, 0.f);
                    v10 = fmaxf(v10, 0.f); v11 = fmaxf(v11, 0.f);
                }
                if (F32OUT) {
                    if (col < N) {
                        *(float2*)(Of + (size_t)r0 * strideO + col) = make_float2(v00, v01);
                        *(float2*)(Of + (size_t)(r0 + 8) * strideO + col) = make_float2(v10, v11);
                    }
                } else {
                    __nv_bfloat16 h00 = __float2bfloat16(v00), h01 = __float2bfloat16(v01);
                    __nv_bfloat16 h10 = __float2bfloat16(v10), h11 = __float2bfloat16(v11);
                    __nv_bfloat16 l00 = __float2bfloat16(v00 - __bfloat162float(h00));
                    __nv_bfloat16 l01 = __float2bfloat16(v01 - __bfloat162float(h01));
                    __nv_bfloat16 l10 = __float2bfloat16(v10 - __bfloat162float(h10));
                    __nv_bfloat16 l11 = __float2bfloat16(v11 - __bfloat162float(h11));
                    uint32_t ph0 = (uint32_t)__bfloat16_as_ushort(h00) | ((uint32_t)__bfloat16_as_ushort(h01) << 16);
                    uint32_t pl0 = (uint32_t)__bfloat16_as_ushort(l00) | ((uint32_t)__bfloat16_as_ushort(l01) << 16);
                    uint32_t ph1 = (uint32_t)__bfloat16_as_ushort(h10) | ((uint32_t)__bfloat16_as_ushort(h11) << 16);
                    uint32_t pl1 = (uint32_t)__bfloat16_as_ushort(l10) | ((uint32_t)__bfloat16_as_ushort(l11) << 16);
                    *(uint32_t*)(Oh + (size_t)r0 * strideO + col) = ph0;
                    *(uint32_t*)(Ol + (size_t)r0 * strideO + col) = pl0;
                    *(uint32_t*)(Oh + (size_t)(r0 + 8) * strideO + col) = ph1;
                    *(uint32_t*)(Ol + (size_t)(r0 + 8) * strideO + col) = pl1;
                }
            }
        }
    }
}

// ---------------------------------------------------------------------------
extern "C" void kernel_launch(void* const* d_in, const int* in_sizes, int n_in,
                              void* d_out, int out_size) {
    const float* x    = (const float*)d_in[0];
    const float* h0   = (const float*)d_in[1];
    const float* W_ih = (const float*)d_in[2];
    const float* W_hh = (const float*)d_in[3];
    const float* b_ih = (const float*)d_in[4];
    const float* b_hh = (const float*)d_in[5];
    const float* w1   = (const float*)d_in[6];
    const float* b1   = (const float*)d_in[7];
    const float* w2   = (const float*)d_in[8];
    const float* b2   = (const float*)d_in[9];
    const float* w3   = (const float*)d_in[10];
    const float* b3   = (const float*)d_in[11];
    const float* w4   = (const float*)d_in[12];
    const float* b4   = (const float*)d_in[13];
    float* out = (float*)d_out;
    float* hid = (out_size >= B_ * T_ + B_) ? out + (size_t)B_ * T_ : nullptr;

    __nv_bfloat16 *ath, *atl, *w1h, *w1l, *w2h, *w2l, *w3h, *w3l, *w4h, *w4l;
    __nv_bfloat16 *y1h, *y1l, *y2h, *y2l, *y3h, *y3l;
    cudaGetSymbolAddress((void**)&ath, g_ath); cudaGetSymbolAddress((void**)&atl, g_atl);
    cudaGetSymbolAddress((void**)&w1h, g_w1h); cudaGetSymbolAddress((void**)&w1l, g_w1l);
    cudaGetSymbolAddress((void**)&w2h, g_w2h); cudaGetSymbolAddress((void**)&w2l, g_w2l);
    cudaGetSymbolAddress((void**)&w3h, g_w3h); cudaGetSymbolAddress((void**)&w3l, g_w3l);
    cudaGetSymbolAddress((void**)&w4h, g_w4h); cudaGetSymbolAddress((void**)&w4l, g_w4l);
    cudaGetSymbolAddress((void**)&y1h, g_y1h); cudaGetSymbolAddress((void**)&y1l, g_y1l);
    cudaGetSymbolAddress((void**)&y2h, g_y2h); cudaGetSymbolAddress((void**)&y2l, g_y2l);
    cudaGetSymbolAddress((void**)&y3h, g_y3h); cudaGetSymbolAddress((void**)&y3l, g_y3l);

    cudaFuncSetAttribute(gemm_mma<true,  false>, cudaFuncAttributeMaxDynamicSharedMemorySize, GEMM_SMEM);
    cudaFuncSetAttribute(gemm_mma<false, true >, cudaFuncAttributeMaxDynamicSharedMemorySize, GEMM_SMEM);

    // 1) input projection (fp32, [T,B])
    proj_kernel<<<dim3((T_ + 31) / 32, B_ / 32), 256>>>(x, W_ih, b_ih, b_hh);
    // 2) recurrence -> g_ath/g_atl [B,TPAD] (transpose fused), hidden -> out tail
    scan_kernel<<<B_ / 256, 256>>>(h0, W_hh, hid);
    // 3) all weight conversions in one launch
    cvt_all<<<dim3((D1_ * T_ + 255) / 256, 4), 256>>>(w1, w2, w3, w4);
    // 4) y1 = relu(hsT @ w1^T + b1)   M=8192 N=1024 K=672
    gemm_mma<true, false><<<dim3(B_ / 128, D1_ / 128), GTHREADS, GEMM_SMEM>>>(
        ath, atl, w1h, w1l, b1, y1h, y1l, nullptr, TPAD, D1_, D1_);
    // 5) y2 = relu(y1 @ w2^T + b2)    K=1024
    gemm_mma<true, false><<<dim3(B_ / 128, D2_ / 128), GTHREADS, GEMM_SMEM>>>(
        y1h, y1l, w2h, w2l, b2, y2h, y2l, nullptr, D1_, D2_, D2_);
    // 6) y3 = relu(y2 @ w3^T + b3)    K=512
    gemm_mma<true, false><<<dim3(B_ / 128, D3_ / 128), GTHREADS, GEMM_SMEM>>>(
        y2h, y2l, w3h, w3l, b3, y3h, y3l, nullptr, D2_, D3_, D3_);
    // 7) out = y3 @ w4^T + b4         K=128, N=658 (masked)
    gemm_mma<false, true><<<dim3(B_ / 128, (T_ + 127) / 128), GTHREADS, GEMM_SMEM>>>(
        y3h, y3l, w4h, w4l, b4, nullptr, nullptr, out, D3_, T_, T_);
}

// round 10
// speedup vs baseline: 1.3663x; 1.1765x over previous
#include <cuda_runtime.h>
#include <cuda_fp16.h>
#include <cstdint>

// ---------------------------------------------------------------------------
// Problem constants
// ---------------------------------------------------------------------------
constexpr int B_   = 8192;
constexpr int T_   = 658;
constexpr int I_   = 7;
constexpr int D1_  = 1024;
constexpr int D2_  = 512;
constexpr int D3_  = 128;
constexpr int XWT  = 688;            // T_ padded for scan prefetch overrun
constexpr int TPAD = 672;            // T_ padded to multiple of 32 (GEMM1 K)

// ---------------------------------------------------------------------------
// Scratch (device globals zero-init; padded regions either rewritten or 0)
// ---------------------------------------------------------------------------
__device__ float   g_xw [(size_t)XWT * B_];     // [T,B] fp32 (rows >= T_ stay 0)
__device__ __half  g_ath[(size_t)B_ * TPAD];    // hs^T hi  [B,TPAD]
__device__ __half  g_atl[(size_t)B_ * TPAD];    // hs^T lo

__device__ __half  g_w1h[(size_t)D1_ * TPAD];   // weights: single fp16
__device__ __half  g_w2h[(size_t)D2_ * D1_ ];
__device__ __half  g_w3h[(size_t)D3_ * D2_ ];
__device__ __half  g_w4h[(size_t)T_  * D3_ ];

__device__ __half  g_y1h[(size_t)B_ * D1_], g_y1l[(size_t)B_ * D1_];
__device__ __half  g_y2h[(size_t)B_ * D2_], g_y2l[(size_t)B_ * D2_];
__device__ __half  g_y3h[(size_t)B_ * D3_], g_y3l[(size_t)B_ * D3_];

// ---------------------------------------------------------------------------
// PTX helpers (base-target ISA only: ldmatrix / mma.sync / cp.async)
// ---------------------------------------------------------------------------
__device__ __forceinline__ uint32_t smem_u32(const void* p) {
    uint32_t a;
    asm("{ .reg .u64 t; cvta.to.shared.u64 t, %1; cvt.u32.u64 %0, t; }" : "=r"(a) : "l"(p));
    return a;
}

__device__ __forceinline__ void cp16(uint32_t dst, const void* src, int srcsize) {
    asm volatile("cp.async.cg.shared.global [%0], [%1], 16, %2;"
                 :: "r"(dst), "l"(src), "r"(srcsize));
}
#define CP_COMMIT() asm volatile("cp.async.commit_group;" ::: "memory")
#define CP_WAIT(n)  asm volatile("cp.async.wait_group %0;" :: "n"(n) : "memory")

#define LDSM4(r, a)                                                             \
    asm volatile("ldmatrix.sync.aligned.m8n8.x4.shared.b16 {%0,%1,%2,%3}, [%4];"\
                 : "=r"((r)[0]), "=r"((r)[1]), "=r"((r)[2]), "=r"((r)[3])       \
                 : "r"(a))

__device__ __forceinline__ void mma16816(float* d, const uint32_t* a,
                                         uint32_t b0, uint32_t b1) {
    asm volatile("mma.sync.aligned.m16n8k16.row.col.f32.f16.f16.f32 "
                 "{%0,%1,%2,%3}, {%4,%5,%6,%7}, {%8,%9}, {%0,%1,%2,%3};"
                 : "+f"(d[0]), "+f"(d[1]), "+f"(d[2]), "+f"(d[3])
                 : "r"(a[0]), "r"(a[1]), "r"(a[2]), "r"(a[3]), "r"(b0), "r"(b1));
}

// ---------------------------------------------------------------------------
// Stage 1: xw[t,b] = dot(x[b,t,:], W_ih) + b_ih + b_hh   ([T,B] fp32)
// ---------------------------------------------------------------------------
__global__ void proj_kernel(const float* __restrict__ x,
                            const float* __restrict__ W_ih,
                            const float* __restrict__ b_ih,
                            const float* __restrict__ b_hh) {
    __shared__ float xs[32][225];
    const int t0 = blockIdx.x * 32;
    const int b0 = blockIdx.y * 32;
    const int tid = threadIdx.x;
    const int tlim = min(32, T_ - t0);
    const int nfl = tlim * I_;

    for (int i = tid; i < 32 * 224; i += 256) {
        int bl = i / 224;
        int off = i - bl * 224;
        float v = 0.f;
        if (off < nfl) v = x[((size_t)(b0 + bl) * T_ + t0) * I_ + off];
        xs[bl][off] = v;
    }
    __syncthreads();

    float w[7];
#pragma unroll
    for (int j = 0; j < 7; ++j) w[j] = W_ih[j];
    const float bias = b_ih[0] + b_hh[0];

    for (int i = tid; i < 1024; i += 256) {
        int bl = i & 31;
        int tl = i >> 5;
        if (tl < tlim) {
            const float* row = &xs[bl][tl * 7];
            float s = bias;
#pragma unroll
            for (int j = 0; j < 7; ++j) s = fmaf(row[j], w[j], s);
            g_xw[(size_t)(t0 + tl) * B_ + (b0 + bl)] = s;
        }
    }
}

// ---------------------------------------------------------------------------
// Stage 2: scalar tanh recurrence -> g_ath/g_atl [B,TPAD] fp16 hi/lo direct.
// ---------------------------------------------------------------------------
__device__ __forceinline__ float tanh_fast(float xv) {
    float ax = fabsf(xv);
    float e = __expf(-2.0f * ax);
    float r = __fdividef(1.0f - e, 1.0f + e);
    return copysignf(r, xv);
}

__device__ __forceinline__ uint32_t pack_hilo(float v) {
    __half h = __float2half_rn(v);
    __half l = __float2half_rn(v - __half2float(h));
    return (uint32_t)__half_as_ushort(h) | ((uint32_t)__half_as_ushort(l) << 16);
}

__global__ void __launch_bounds__(256)
scan_kernel(const float* __restrict__ h0,
            const float* __restrict__ W_hh,
            float* __restrict__ hid) {
    __shared__ uint32_t sh[256][33];
    const int tid = threadIdx.x;
    const int b0 = blockIdx.x * 256;
    const int b  = b0 + tid;

    const float whh = W_hh[0];
    const float* xp = g_xw + b;
    float h = h0[b];
    float hT = h;

    float bufA[16], bufB[16];
#pragma unroll
    for (int j = 0; j < 16; ++j) bufA[j] = xp[(size_t)j * B_];

    for (int tc = 0; tc < TPAD; tc += 32) {
#pragma unroll
        for (int j = 0; j < 16; ++j) bufB[j] = xp[(size_t)(tc + 16 + j) * B_];
#pragma unroll
        for (int j = 0; j < 16; ++j) {
            h = tanh_fast(fmaf(h, whh, bufA[j]));
            sh[tid][j] = pack_hilo(h);
            if (tc + j == T_ - 1) hT = h;
        }
#pragma unroll
        for (int j = 0; j < 16; ++j) bufA[j] = xp[(size_t)(tc + 32 + j) * B_];  // max 687 < XWT
#pragma unroll
        for (int j = 0; j < 16; ++j) {
            h = tanh_fast(fmaf(h, whh, bufB[j]));
            sh[tid][16 + j] = pack_hilo(h);
            if (tc + 16 + j == T_ - 1) hT = h;
        }
        __syncthreads();
#pragma unroll
        for (int it = 0; it < 16; ++it) {
            int lin = it * 256 + tid;
            int r = lin >> 4;
            int p = lin & 15;
            uint32_t v0 = sh[r][2 * p];
            uint32_t v1 = sh[r][2 * p + 1];
            size_t o = (size_t)(b0 + r) * TPAD + tc + 2 * p;
            *(uint32_t*)(g_ath + o) = (v0 & 0xffffu) | (v1 << 16);
            *(uint32_t*)(g_atl + o) = (v0 >> 16) | (v1 & 0xffff0000u);
        }
        __syncthreads();
    }
    if (hid) hid[b] = hT;
}

// ---------------------------------------------------------------------------
// Weight conversion (single fp16), all 4 layers in one launch
// ---------------------------------------------------------------------------
__device__ __forceinline__ void cvt_seg(const float* __restrict__ src,
                                        __half* __restrict__ hi,
                                        int R, int K, int Kp, int i) {
    if (i < R * K) {
        int r = i / K, k = i - r * K;
        hi[(size_t)r * Kp + k] = __float2half_rn(src[i]);
    }
}

__global__ void cvt_all(const float* __restrict__ w1, const float* __restrict__ w2,
                        const float* __restrict__ w3, const float* __restrict__ w4) {
    int i = blockIdx.x * 256 + threadIdx.x;
    switch (blockIdx.y) {
        case 0: cvt_seg(w1, g_w1h, D1_, T_,  TPAD, i); break;
        case 1: cvt_seg(w2, g_w2h, D2_, D1_, D1_,  i); break;
        case 2: cvt_seg(w3, g_w3h, D3_, D2_, D2_,  i); break;
        case 3: cvt_seg(w4, g_w4h, T_,  D3_, D3_,  i); break;
    }
}

// ---------------------------------------------------------------------------
// mma.sync GEMM: C[M,N] = act(A * B^T + bias), fp16 2-term (Ah+Al) x Bh.
//   CTA tile 128 x (2*WN), BK=32, 4 warps (2x2), warp tile 64 x WN.
//   2-stage cp.async pipeline, SINGLE __syncthreads per chunk.
// ---------------------------------------------------------------------------
constexpr int PITCH  = 80;
constexpr int MATSZA = 128 * PITCH;      // 10240 (Ah, Al each)

constexpr int STAGE_SZ_128 = 2 * MATSZA + 128 * PITCH;   // 30720
constexpr int STAGE_SZ_64  = 2 * MATSZA +  64 * PITCH;   // 25600
constexpr int SMEM_128     = 2 * STAGE_SZ_128;           // 61440
constexpr int SMEM_64      = 2 * STAGE_SZ_64;            // 51200

template <int BN>
__device__ __forceinline__ void load_stage(
        uint32_t sbase, int slot, int k0, int tid,
        const __half* Ah, const __half* Al, const __half* Bh,
        int K, int N, int bm, int bn) {
    constexpr int SSZ = (BN == 128) ? STAGE_SZ_128 : STAGE_SZ_64;
    const uint32_t dstb = sbase + slot * SSZ;
#pragma unroll
    for (int it = 0; it < (256 + BN) * 4 / 128; ++it) {
        int i = tid + it * 128;
        if (i < 1024) {
            int mat = i >> 9;              // 0:Ah 1:Al
            int row = (i >> 2) & 127;
            int seg = i & 3;
            const __half* src = (mat == 0 ? Ah : Al) + (size_t)(bm + row) * K + k0 + seg * 8;
            cp16(dstb + mat * MATSZA + row * PITCH + seg * 16, src, 16);
        } else {
            int j = i - 1024;
            int row = j >> 2;              // 0..BN-1
            int seg = j & 3;
            int n = bn + row;
            const __half* src;
            int size = 16;
            if (n < N) {
                src = Bh + (size_t)n * K + k0 + seg * 8;
            } else {
                src = Bh + k0 + seg * 8;
                size = 0;
            }
            cp16(dstb + 2 * MATSZA + row * PITCH + seg * 16, src, size);
        }
    }
}

template <int WN, bool RELU, bool F32OUT>
__global__ void __launch_bounds__(128)
gemm_mma(const __half* __restrict__ Ah, const __half* __restrict__ Al,
         const __half* __restrict__ Bh,
         const float* __restrict__ bias,
         __half* __restrict__ Oh, __half* __restrict__ Ol,
         float* __restrict__ Of,
         int K, int N, int strideO) {
    constexpr int BN = 2 * WN;
    constexpr int NP = WN / 16;
    constexpr int SSZ = (BN == 128) ? STAGE_SZ_128 : STAGE_SZ_64;
    extern __shared__ char smem[];
    const uint32_t sbase = smem_u32(smem);
    const int tid = threadIdx.x;
    const int lane = tid & 31;
    const int wid = tid >> 5;       // 0..3
    const int wm = wid & 1;         // 2 warps over M (64 rows each)
    const int wn = wid >> 1;        // 2 warps over N (WN cols each)
    const int bm = blockIdx.x * 128;
    const int bn = blockIdx.y * BN;
    const int nk = K >> 5;

    float acc[4][2 * NP][4];
#pragma unroll
    for (int i = 0; i < 4; ++i)
#pragma unroll
        for (int j = 0; j < 2 * NP; ++j)
#pragma unroll
            for (int q = 0; q < 4; ++q) acc[i][j][q] = 0.f;

    const uint32_t a_addr = sbase + (wm * 64 + (lane & 15)) * PITCH + (lane >> 4) * 16;
    const uint32_t b_addr = sbase + 2 * MATSZA +
        (wn * WN + (lane & 7) + ((lane >> 4) * 8)) * PITCH + ((lane >> 3) & 1) * 16;

    load_stage<BN>(sbase, 0, 0, tid, Ah, Al, Bh, K, N, bm, bn);
    CP_COMMIT();

    for (int kc = 0; kc < nk; ++kc) {
        CP_WAIT(0);
        __syncthreads();            // stage kc visible AND prev-stage reads done
        if (kc + 1 < nk) {
            load_stage<BN>(sbase, (kc + 1) & 1, (kc + 1) * 32, tid, Ah, Al, Bh, K, N, bm, bn);
            CP_COMMIT();
        }

        const uint32_t st = (uint32_t)(kc & 1) * SSZ;
#pragma unroll
        for (int kk = 0; kk < 2; ++kk) {
            const uint32_t ko = kk * 32;
            uint32_t aH[4][4], aL[4][4];
#pragma unroll
            for (int mi = 0; mi < 4; ++mi) {
                LDSM4(aH[mi], a_addr + st + mi * (16 * PITCH) + ko);
                LDSM4(aL[mi], a_addr + st + MATSZA + mi * (16 * PITCH) + ko);
            }
            uint32_t bR[NP][4];
#pragma unroll
            for (int np = 0; np < NP; ++np)
                LDSM4(bR[np], b_addr + st + np * (16 * PITCH) + ko);
            // pass 1: Ah x B
#pragma unroll
            for (int mi = 0; mi < 4; ++mi)
#pragma unroll
                for (int np = 0; np < NP; ++np) {
                    mma16816(acc[mi][np * 2],     aH[mi], bR[np][0], bR[np][1]);
                    mma16816(acc[mi][np * 2 + 1], aH[mi], bR[np][2], bR[np][3]);
                }
            // pass 2: Al x B
#pragma unroll
            for (int mi = 0; mi < 4; ++mi)
#pragma unroll
                for (int np = 0; np < NP; ++np) {
                    mma16816(acc[mi][np * 2],     aL[mi], bR[np][0], bR[np][1]);
                    mma16816(acc[mi][np * 2 + 1], aL[mi], bR[np][2], bR[np][3]);
                }
        }
    }

    // Epilogue
    const int g = lane >> 2, tig = lane & 3;
#pragma unroll
    for (int mi = 0; mi < 4; ++mi) {
#pragma unroll
        for (int np = 0; np < NP; ++np) {
#pragma unroll
            for (int c = 0; c < 2; ++c) {
                int col = bn + wn * WN + np * 16 + c * 8 + 2 * tig;
                float b0 = 0.f, b1 = 0.f;
                if (col < N) { b0 = bias[col]; b1 = bias[col + 1]; }
                float* a = acc[mi][np * 2 + c];
                int r0 = bm + wm * 64 + mi * 16 + g;
                float v00 = a[0] + b0, v01 = a[1] + b1;
                float v10 = a[2] + b0, v11 = a[3] + b1;
                if (RELU) {
                    v00 = fmaxf(v00, 0.f); v01 = fmaxf(v01, 0.f);
                    v10 = fmaxf(v10, 0.f); v11 = fmaxf(v11, 0.f);
                }
                if (F32OUT) {
                    if (col < N) {
                        *(float2*)(Of + (size_t)r0 * strideO + col) = make_float2(v00, v01);
                        *(float2*)(Of + (size_t)(r0 + 8) * strideO + col) = make_float2(v10, v11);
                    }
                } else {
                    __half h00 = __float2half_rn(v00), h01 = __float2half_rn(v01);
                    __half h10 = __float2half_rn(v10), h11 = __float2half_rn(v11);
                    __half l00 = __float2half_rn(v00 - __half2float(h00));
                    __half l01 = __float2half_rn(v01 - __half2float(h01));
                    __half l10 = __float2half_rn(v10 - __half2float(h10));
                    __half l11 = __float2half_rn(v11 - __half2float(h11));
                    uint32_t ph0 = (uint32_t)__half_as_ushort(h00) | ((uint32_t)__half_as_ushort(h01) << 16);
                    uint32_t pl0 = (uint32_t)__half_as_ushort(l00) | ((uint32_t)__half_as_ushort(l01) << 16);
                    uint32_t ph1 = (uint32_t)__half_as_ushort(h10) | ((uint32_t)__half_as_ushort(h11) << 16);
                    uint32_t pl1 = (uint32_t)__half_as_ushort(l10) | ((uint32_t)__half_as_ushort(l11) << 16);
                    *(uint32_t*)(Oh + (size_t)r0 * strideO + col) = ph0;
                    *(uint32_t*)(Ol + (size_t)r0 * strideO + col) = pl0;
                    *(uint32_t*)(Oh + (size_t)(r0 + 8) * strideO + col) = ph1;
                    *(uint32_t*)(Ol + (size_t)(r0 + 8) * strideO + col) = pl1;
                }
            }
        }
    }
}

// ---------------------------------------------------------------------------
extern "C" void kernel_launch(void* const* d_in, const int* in_sizes, int n_in,
                              void* d_out, int out_size) {
    const float* x    = (const float*)d_in[0];
    const float* h0   = (const float*)d_in[1];
    const float* W_ih = (const float*)d_in[2];
    const float* W_hh = (const float*)d_in[3];
    const float* b_ih = (const float*)d_in[4];
    const float* b_hh = (const float*)d_in[5];
    const float* w1   = (const float*)d_in[6];
    const float* b1   = (const float*)d_in[7];
    const float* w2   = (const float*)d_in[8];
    const float* b2   = (const float*)d_in[9];
    const float* w3   = (const float*)d_in[10];
    const float* b3   = (const float*)d_in[11];
    const float* w4   = (const float*)d_in[12];
    const float* b4   = (const float*)d_in[13];
    float* out = (float*)d_out;
    float* hid = (out_size >= B_ * T_ + B_) ? out + (size_t)B_ * T_ : nullptr;

    __half *ath, *atl, *w1h, *w2h, *w3h, *w4h;
    __half *y1h, *y1l, *y2h, *y2l, *y3h, *y3l;
    cudaGetSymbolAddress((void**)&ath, g_ath); cudaGetSymbolAddress((void**)&atl, g_atl);
    cudaGetSymbolAddress((void**)&w1h, g_w1h); cudaGetSymbolAddress((void**)&w2h, g_w2h);
    cudaGetSymbolAddress((void**)&w3h, g_w3h); cudaGetSymbolAddress((void**)&w4h, g_w4h);
    cudaGetSymbolAddress((void**)&y1h, g_y1h); cudaGetSymbolAddress((void**)&y1l, g_y1l);
    cudaGetSymbolAddress((void**)&y2h, g_y2h); cudaGetSymbolAddress((void**)&y2l, g_y2l);
    cudaGetSymbolAddress((void**)&y3h, g_y3h); cudaGetSymbolAddress((void**)&y3l, g_y3l);

    cudaFuncSetAttribute(gemm_mma<64, true,  false>, cudaFuncAttributeMaxDynamicSharedMemorySize, SMEM_128);
    cudaFuncSetAttribute(gemm_mma<32, true,  false>, cudaFuncAttributeMaxDynamicSharedMemorySize, SMEM_64);
    cudaFuncSetAttribute(gemm_mma<32, false, true >, cudaFuncAttributeMaxDynamicSharedMemorySize, SMEM_64);

    // 1) input projection (fp32, [T,B])
    proj_kernel<<<dim3((T_ + 31) / 32, B_ / 32), 256>>>(x, W_ih, b_ih, b_hh);
    // 2) recurrence -> g_ath/g_atl [B,TPAD] fp16 hi/lo, hidden -> out tail
    scan_kernel<<<B_ / 256, 256>>>(h0, W_hh, hid);
    // 3) all weight conversions (single fp16)
    cvt_all<<<dim3((D1_ * T_ + 255) / 256, 4), 256>>>(w1, w2, w3, w4);
    // 4) y1 = relu(hsT @ w1^T + b1)   M=8192 N=1024 K=672, BN=128
    gemm_mma<64, true, false><<<dim3(B_ / 128, D1_ / 128), 128, SMEM_128>>>(
        ath, atl, w1h, b1, y1h, y1l, nullptr, TPAD, D1_, D1_);
    // 5) y2 = relu(y1 @ w2^T + b2)    K=1024, BN=128
    gemm_mma<64, true, false><<<dim3(B_ / 128, D2_ / 128), 128, SMEM_128>>>(
        y1h, y1l, w2h, b2, y2h, y2l, nullptr, D1_, D2_, D2_);
    // 6) y3 = relu(y2 @ w3^T + b3)    K=512, BN=64 -> 128 CTAs
    gemm_mma<32, true, false><<<dim3(B_ / 128, D3_ / 64), 128, SMEM_64>>>(
        y2h, y2l, w3h, b3, y3h, y3l, nullptr, D2_, D3_, D3_);
    // 7) out = y3 @ w4^T + b4         K=128, N=658, BN=64 -> 704 CTAs
    gemm_mma<32, false, true><<<dim3(B_ / 128, (T_ + 63) / 64), 128, SMEM_64>>>(
        y3h, y3l, w4h, b4, nullptr, nullptr, out, D3_, T_, T_);
}

// round 11
// speedup vs baseline: 1.3893x; 1.0168x over previous
#include <cuda_runtime.h>
#include <cuda_fp16.h>
#include <cstdint>

// ---------------------------------------------------------------------------
// Problem constants
// ---------------------------------------------------------------------------
constexpr int B_   = 8192;
constexpr int T_   = 658;
constexpr int I_   = 7;
constexpr int D1_  = 1024;
constexpr int D2_  = 512;
constexpr int D3_  = 128;
constexpr int XWT  = 688;            // T_ padded for scan prefetch overrun
constexpr int TPAD = 672;            // T_ padded to multiple of 32 (GEMM1 K)

// ---------------------------------------------------------------------------
// Scratch (device globals zero-init; padded regions either rewritten or 0)
// ---------------------------------------------------------------------------
__device__ float   g_xw [(size_t)XWT * B_];     // [T,B] fp32 (rows >= T_ stay 0)
__device__ __half  g_ath[(size_t)B_ * TPAD];    // hs^T hi  [B,TPAD]
__device__ __half  g_atl[(size_t)B_ * TPAD];    // hs^T lo

__device__ __half  g_w1h[(size_t)D1_ * TPAD];   // weights: single fp16
__device__ __half  g_w2h[(size_t)D2_ * D1_ ];
__device__ __half  g_w3h[(size_t)D3_ * D2_ ];
__device__ __half  g_w4h[(size_t)T_  * D3_ ];

__device__ __half  g_y1h[(size_t)B_ * D1_], g_y1l[(size_t)B_ * D1_];
__device__ __half  g_y2h[(size_t)B_ * D2_], g_y2l[(size_t)B_ * D2_];
__device__ __half  g_y3h[(size_t)B_ * D3_], g_y3l[(size_t)B_ * D3_];

// ---------------------------------------------------------------------------
// PTX helpers (base-target ISA only: ldmatrix / mma.sync / cp.async)
// ---------------------------------------------------------------------------
__device__ __forceinline__ uint32_t smem_u32(const void* p) {
    uint32_t a;
    asm("{ .reg .u64 t; cvta.to.shared.u64 t, %1; cvt.u32.u64 %0, t; }" : "=r"(a) : "l"(p));
    return a;
}

__device__ __forceinline__ void cp16(uint32_t dst, const void* src, int srcsize) {
    asm volatile("cp.async.cg.shared.global [%0], [%1], 16, %2;"
                 :: "r"(dst), "l"(src), "r"(srcsize));
}
#define CP_COMMIT() asm volatile("cp.async.commit_group;" ::: "memory")
#define CP_WAIT(n)  asm volatile("cp.async.wait_group %0;" :: "n"(n) : "memory")

#define LDSM4(r, a)                                                             \
    asm volatile("ldmatrix.sync.aligned.m8n8.x4.shared.b16 {%0,%1,%2,%3}, [%4];"\
                 : "=r"((r)[0]), "=r"((r)[1]), "=r"((r)[2]), "=r"((r)[3])       \
                 : "r"(a))

__device__ __forceinline__ void mma16816(float* d, const uint32_t* a,
                                         uint32_t b0, uint32_t b1) {
    asm volatile("mma.sync.aligned.m16n8k16.row.col.f32.f16.f16.f32 "
                 "{%0,%1,%2,%3}, {%4,%5,%6,%7}, {%8,%9}, {%0,%1,%2,%3};"
                 : "+f"(d[0]), "+f"(d[1]), "+f"(d[2]), "+f"(d[3])
                 : "r"(a[0]), "r"(a[1]), "r"(a[2]), "r"(a[3]), "r"(b0), "r"(b1));
}

// ---------------------------------------------------------------------------
// Stage 1: xw[t,b] = dot(x[b,t,:], W_ih) + b_ih + b_hh   ([T,B] fp32)
// ---------------------------------------------------------------------------
__global__ void proj_kernel(const float* __restrict__ x,
                            const float* __restrict__ W_ih,
                            const float* __restrict__ b_ih,
                            const float* __restrict__ b_hh) {
    __shared__ float xs[32][225];
    const int t0 = blockIdx.x * 32;
    const int b0 = blockIdx.y * 32;
    const int tid = threadIdx.x;
    const int tlim = min(32, T_ - t0);
    const int nfl = tlim * I_;

    for (int i = tid; i < 32 * 224; i += 256) {
        int bl = i / 224;
        int off = i - bl * 224;
        float v = 0.f;
        if (off < nfl) v = x[((size_t)(b0 + bl) * T_ + t0) * I_ + off];
        xs[bl][off] = v;
    }
    __syncthreads();

    float w[7];
#pragma unroll
    for (int j = 0; j < 7; ++j) w[j] = W_ih[j];
    const float bias = b_ih[0] + b_hh[0];

    for (int i = tid; i < 1024; i += 256) {
        int bl = i & 31;
        int tl = i >> 5;
        if (tl < tlim) {
            const float* row = &xs[bl][tl * 7];
            float s = bias;
#pragma unroll
            for (int j = 0; j < 7; ++j) s = fmaf(row[j], w[j], s);
            g_xw[(size_t)(t0 + tl) * B_ + (b0 + bl)] = s;
        }
    }
}

// ---------------------------------------------------------------------------
// Stage 2: scalar tanh recurrence -> g_ath/g_atl [B,TPAD] fp16 hi/lo direct.
// ---------------------------------------------------------------------------
__device__ __forceinline__ float tanh_fast(float xv) {
    float ax = fabsf(xv);
    float e = __expf(-2.0f * ax);
    float r = __fdividef(1.0f - e, 1.0f + e);
    return copysignf(r, xv);
}

__device__ __forceinline__ uint32_t pack_hilo(float v) {
    __half h = __float2half_rn(v);
    __half l = __float2half_rn(v - __half2float(h));
    return (uint32_t)__half_as_ushort(h) | ((uint32_t)__half_as_ushort(l) << 16);
}

__global__ void __launch_bounds__(256)
scan_kernel(const float* __restrict__ h0,
            const float* __restrict__ W_hh,
            float* __restrict__ hid) {
    __shared__ uint32_t sh[256][33];
    const int tid = threadIdx.x;
    const int b0 = blockIdx.x * 256;
    const int b  = b0 + tid;

    const float whh = W_hh[0];
    const float* xp = g_xw + b;
    float h = h0[b];
    float hT = h;

    float bufA[16], bufB[16];
#pragma unroll
    for (int j = 0; j < 16; ++j) bufA[j] = xp[(size_t)j * B_];

    for (int tc = 0; tc < TPAD; tc += 32) {
#pragma unroll
        for (int j = 0; j < 16; ++j) bufB[j] = xp[(size_t)(tc + 16 + j) * B_];
#pragma unroll
        for (int j = 0; j < 16; ++j) {
            h = tanh_fast(fmaf(h, whh, bufA[j]));
            sh[tid][j] = pack_hilo(h);
            if (tc + j == T_ - 1) hT = h;
        }
#pragma unroll
        for (int j = 0; j < 16; ++j) bufA[j] = xp[(size_t)(tc + 32 + j) * B_];  // max 687 < XWT
#pragma unroll
        for (int j = 0; j < 16; ++j) {
            h = tanh_fast(fmaf(h, whh, bufB[j]));
            sh[tid][16 + j] = pack_hilo(h);
            if (tc + 16 + j == T_ - 1) hT = h;
        }
        __syncthreads();
#pragma unroll
        for (int it = 0; it < 16; ++it) {
            int lin = it * 256 + tid;
            int r = lin >> 4;
            int p = lin & 15;
            uint32_t v0 = sh[r][2 * p];
            uint32_t v1 = sh[r][2 * p + 1];
            size_t o = (size_t)(b0 + r) * TPAD + tc + 2 * p;
            *(uint32_t*)(g_ath + o) = (v0 & 0xffffu) | (v1 << 16);
            *(uint32_t*)(g_atl + o) = (v0 >> 16) | (v1 & 0xffff0000u);
        }
        __syncthreads();
    }
    if (hid) hid[b] = hT;
}

// ---------------------------------------------------------------------------
// Weight conversion (single fp16), all 4 layers in one launch
// ---------------------------------------------------------------------------
__device__ __forceinline__ void cvt_seg(const float* __restrict__ src,
                                        __half* __restrict__ hi,
                                        int R, int K, int Kp, int i) {
    if (i < R * K) {
        int r = i / K, k = i - r * K;
        hi[(size_t)r * Kp + k] = __float2half_rn(src[i]);
    }
}

__global__ void cvt_all(const float* __restrict__ w1, const float* __restrict__ w2,
                        const float* __restrict__ w3, const float* __restrict__ w4) {
    int i = blockIdx.x * 256 + threadIdx.x;
    switch (blockIdx.y) {
        case 0: cvt_seg(w1, g_w1h, D1_, T_,  TPAD, i); break;
        case 1: cvt_seg(w2, g_w2h, D2_, D1_, D1_,  i); break;
        case 2: cvt_seg(w3, g_w3h, D3_, D2_, D2_,  i); break;
        case 3: cvt_seg(w4, g_w4h, T_,  D3_, D3_,  i); break;
    }
}

// ---------------------------------------------------------------------------
// mma.sync GEMM: C[M,N] = act(A * B^T + bias), fp16 2-term (Ah+Al) x Bh.
//   CTA tile 128 x (2*WN), BK=32, 4 warps (2x2), warp tile 64 x WN.
//   3-stage cp.async pipeline (CP_WAIT(1): ~2 chunk windows per load),
//   2 CTAs/SM (3*30720*2 = 184KB < 228KB), __launch_bounds__(128,2).
// ---------------------------------------------------------------------------
constexpr int PITCH  = 80;
constexpr int MATSZA = 128 * PITCH;      // 10240 (Ah, Al each)

constexpr int STAGE_SZ_128 = 2 * MATSZA + 128 * PITCH;   // 30720
constexpr int STAGE_SZ_64  = 2 * MATSZA +  64 * PITCH;   // 25600
constexpr int SMEM_128     = 3 * STAGE_SZ_128;           // 92160
constexpr int SMEM_64      = 3 * STAGE_SZ_64;            // 76800

template <int BN>
__device__ __forceinline__ void load_stage(
        uint32_t sbase, int slot, int k0, int tid,
        const __half* Ah, const __half* Al, const __half* Bh,
        int K, int N, int bm, int bn) {
    constexpr int SSZ = (BN == 128) ? STAGE_SZ_128 : STAGE_SZ_64;
    const uint32_t dstb = sbase + slot * SSZ;
#pragma unroll
    for (int it = 0; it < (256 + BN) * 4 / 128; ++it) {
        int i = tid + it * 128;
        if (i < 1024) {
            int mat = i >> 9;              // 0:Ah 1:Al
            int row = (i >> 2) & 127;
            int seg = i & 3;
            const __half* src = (mat == 0 ? Ah : Al) + (size_t)(bm + row) * K + k0 + seg * 8;
            cp16(dstb + mat * MATSZA + row * PITCH + seg * 16, src, 16);
        } else {
            int j = i - 1024;
            int row = j >> 2;              // 0..BN-1
            int seg = j & 3;
            int n = bn + row;
            const __half* src;
            int size = 16;
            if (n < N) {
                src = Bh + (size_t)n * K + k0 + seg * 8;
            } else {
                src = Bh + k0 + seg * 8;
                size = 0;
            }
            cp16(dstb + 2 * MATSZA + row * PITCH + seg * 16, src, size);
        }
    }
}

template <int WN, bool RELU, bool F32OUT>
__global__ void __launch_bounds__(128, 2)
gemm_mma(const __half* __restrict__ Ah, const __half* __restrict__ Al,
         const __half* __restrict__ Bh,
         const float* __restrict__ bias,
         __half* __restrict__ Oh, __half* __restrict__ Ol,
         float* __restrict__ Of,
         int K, int N, int strideO) {
    constexpr int BN = 2 * WN;
    constexpr int NP = WN / 16;
    constexpr int SSZ = (BN == 128) ? STAGE_SZ_128 : STAGE_SZ_64;
    extern __shared__ char smem[];
    const uint32_t sbase = smem_u32(smem);
    const int tid = threadIdx.x;
    const int lane = tid & 31;
    const int wid = tid >> 5;       // 0..3
    const int wm = wid & 1;         // 2 warps over M (64 rows each)
    const int wn = wid >> 1;        // 2 warps over N (WN cols each)
    const int bm = blockIdx.x * 128;
    const int bn = blockIdx.y * BN;
    const int nk = K >> 5;

    float acc[4][2 * NP][4];
#pragma unroll
    for (int i = 0; i < 4; ++i)
#pragma unroll
        for (int j = 0; j < 2 * NP; ++j)
#pragma unroll
            for (int q = 0; q < 4; ++q) acc[i][j][q] = 0.f;

    const uint32_t a_addr = sbase + (wm * 64 + (lane & 15)) * PITCH + (lane >> 4) * 16;
    const uint32_t b_addr = sbase + 2 * MATSZA +
        (wn * WN + (lane & 7) + ((lane >> 4) * 8)) * PITCH + ((lane >> 3) & 1) * 16;

    // prologue: 2 stages in flight
    load_stage<BN>(sbase, 0, 0, tid, Ah, Al, Bh, K, N, bm, bn);
    CP_COMMIT();
    if (nk > 1) {
        load_stage<BN>(sbase, 1, 32, tid, Ah, Al, Bh, K, N, bm, bn);
        CP_COMMIT();
    }

    int slot = 0;
    for (int kc = 0; kc < nk; ++kc) {
        if (kc + 1 < nk) { CP_WAIT(1); } else { CP_WAIT(0); }
        __syncthreads();            // stage kc visible; slot (kc+2)%3 fully read
        if (kc + 2 < nk) {
            int ns = slot + 2; if (ns >= 3) ns -= 3;
            load_stage<BN>(sbase, ns, (kc + 2) * 32, tid, Ah, Al, Bh, K, N, bm, bn);
            CP_COMMIT();
        }

        const uint32_t st = (uint32_t)slot * SSZ;
        if (++slot == 3) slot = 0;
#pragma unroll
        for (int kk = 0; kk < 2; ++kk) {
            const uint32_t ko = kk * 32;
            uint32_t aH[4][4], aL[4][4];
#pragma unroll
            for (int mi = 0; mi < 4; ++mi) {
                LDSM4(aH[mi], a_addr + st + mi * (16 * PITCH) + ko);
                LDSM4(aL[mi], a_addr + st + MATSZA + mi * (16 * PITCH) + ko);
            }
            uint32_t bR[NP][4];
#pragma unroll
            for (int np = 0; np < NP; ++np)
                LDSM4(bR[np], b_addr + st + np * (16 * PITCH) + ko);
            // pass 1: Ah x B
#pragma unroll
            for (int mi = 0; mi < 4; ++mi)
#pragma unroll
                for (int np = 0; np < NP; ++np) {
                    mma16816(acc[mi][np * 2],     aH[mi], bR[np][0], bR[np][1]);
                    mma16816(acc[mi][np * 2 + 1], aH[mi], bR[np][2], bR[np][3]);
                }
            // pass 2: Al x B
#pragma unroll
            for (int mi = 0; mi < 4; ++mi)
#pragma unroll
                for (int np = 0; np < NP; ++np) {
                    mma16816(acc[mi][np * 2],     aL[mi], bR[np][0], bR[np][1]);
                    mma16816(acc[mi][np * 2 + 1], aL[mi], bR[np][2], bR[np][3]);
                }
        }
    }

    // Epilogue
    const int g = lane >> 2, tig = lane & 3;
#pragma unroll
    for (int mi = 0; mi < 4; ++mi) {
#pragma unroll
        for (int np = 0; np < NP; ++np) {
#pragma unroll
            for (int c = 0; c < 2; ++c) {
                int col = bn + wn * WN + np * 16 + c * 8 + 2 * tig;
                float b0 = 0.f, b1 = 0.f;
                if (col < N) { b0 = bias[col]; b1 = bias[col + 1]; }
                float* a = acc[mi][np * 2 + c];
                int r0 = bm + wm * 64 + mi * 16 + g;
                float v00 = a[0] + b0, v01 = a[1] + b1;
                float v10 = a[2] + b0, v11 = a[3] + b1;
                if (RELU) {
                    v00 = fmaxf(v00, 0.f); v01 = fmaxf(v01, 0.f);
                    v10 = fmaxf(v10, 0.f); v11 = fmaxf(v11, 0.f);
                }
                if (F32OUT) {
                    if (col < N) {
                        *(float2*)(Of + (size_t)r0 * strideO + col) = make_float2(v00, v01);
                        *(float2*)(Of + (size_t)(r0 + 8) * strideO + col) = make_float2(v10, v11);
                    }
                } else {
                    __half h00 = __float2half_rn(v00), h01 = __float2half_rn(v01);
                    __half h10 = __float2half_rn(v10), h11 = __float2half_rn(v11);
                    __half l00 = __float2half_rn(v00 - __half2float(h00));
                    __half l01 = __float2half_rn(v01 - __half2float(h01));
                    __half l10 = __float2half_rn(v10 - __half2float(h10));
                    __half l11 = __float2half_rn(v11 - __half2float(h11));
                    uint32_t ph0 = (uint32_t)__half_as_ushort(h00) | ((uint32_t)__half_as_ushort(h01) << 16);
                    uint32_t pl0 = (uint32_t)__half_as_ushort(l00) | ((uint32_t)__half_as_ushort(l01) << 16);
                    uint32_t ph1 = (uint32_t)__half_as_ushort(h10) | ((uint32_t)__half_as_ushort(h11) << 16);
                    uint32_t pl1 = (uint32_t)__half_as_ushort(l10) | ((uint32_t)__half_as_ushort(l11) << 16);
                    *(uint32_t*)(Oh + (size_t)r0 * strideO + col) = ph0;
                    *(uint32_t*)(Ol + (size_t)r0 * strideO + col) = pl0;
                    *(uint32_t*)(Oh + (size_t)(r0 + 8) * strideO + col) = ph1;
                    *(uint32_t*)(Ol + (size_t)(r0 + 8) * strideO + col) = pl1;
                }
            }
        }
    }
}

// ---------------------------------------------------------------------------
extern "C" void kernel_launch(void* const* d_in, const int* in_sizes, int n_in,
                              void* d_out, int out_size) {
    const float* x    = (const float*)d_in[0];
    const float* h0   = (const float*)d_in[1];
    const float* W_ih = (const float*)d_in[2];
    const float* W_hh = (const float*)d_in[3];
    const float* b_ih = (const float*)d_in[4];
    const float* b_hh = (const float*)d_in[5];
    const float* w1   = (const float*)d_in[6];
    const float* b1   = (const float*)d_in[7];
    const float* w2   = (const float*)d_in[8];
    const float* b2   = (const float*)d_in[9];
    const float* w3   = (const float*)d_in[10];
    const float* b3   = (const float*)d_in[11];
    const float* w4   = (const float*)d_in[12];
    const float* b4   = (const float*)d_in[13];
    float* out = (float*)d_out;
    float* hid = (out_size >= B_ * T_ + B_) ? out + (size_t)B_ * T_ : nullptr;

    __half *ath, *atl, *w1h, *w2h, *w3h, *w4h;
    __half *y1h, *y1l, *y2h, *y2l, *y3h, *y3l;
    cudaGetSymbolAddress((void**)&ath, g_ath); cudaGetSymbolAddress((void**)&atl, g_atl);
    cudaGetSymbolAddress((void**)&w1h, g_w1h); cudaGetSymbolAddress((void**)&w2h, g_w2h);
    cudaGetSymbolAddress((void**)&w3h, g_w3h); cudaGetSymbolAddress((void**)&w4h, g_w4h);
    cudaGetSymbolAddress((void**)&y1h, g_y1h); cudaGetSymbolAddress((void**)&y1l, g_y1l);
    cudaGetSymbolAddress((void**)&y2h, g_y2h); cudaGetSymbolAddress((void**)&y2l, g_y2l);
    cudaGetSymbolAddress((void**)&y3h, g_y3h); cudaGetSymbolAddress((void**)&y3l, g_y3l);

    cudaFuncSetAttribute(gemm_mma<64, true,  false>, cudaFuncAttributeMaxDynamicSharedMemorySize, SMEM_128);
    cudaFuncSetAttribute(gemm_mma<32, true,  false>, cudaFuncAttributeMaxDynamicSharedMemorySize, SMEM_64);
    cudaFuncSetAttribute(gemm_mma<32, false, true >, cudaFuncAttributeMaxDynamicSharedMemorySize, SMEM_64);

    // 1) input projection (fp32, [T,B])
    proj_kernel<<<dim3((T_ + 31) / 32, B_ / 32), 256>>>(x, W_ih, b_ih, b_hh);
    // 2) recurrence -> g_ath/g_atl [B,TPAD] fp16 hi/lo, hidden -> out tail
    scan_kernel<<<B_ / 256, 256>>>(h0, W_hh, hid);
    // 3) all weight conversions (single fp16)
    cvt_all<<<dim3((D1_ * T_ + 255) / 256, 4), 256>>>(w1, w2, w3, w4);
    // 4) y1 = relu(hsT @ w1^T + b1)   M=8192 N=1024 K=672, BN=128
    gemm_mma<64, true, false><<<dim3(B_ / 128, D1_ / 128), 128, SMEM_128>>>(
        ath, atl, w1h, b1, y1h, y1l, nullptr, TPAD, D1_, D1_);
    // 5) y2 = relu(y1 @ w2^T + b2)    K=1024, BN=128
    gemm_mma<64, true, false><<<dim3(B_ / 128, D2_ / 128), 128, SMEM_128>>>(
        y1h, y1l, w2h, b2, y2h, y2l, nullptr, D1_, D2_, D2_);
    // 6) y3 = relu(y2 @ w3^T + b3)    K=512, BN=64 -> 128 CTAs
    gemm_mma<32, true, false><<<dim3(B_ / 128, D3_ / 64), 128, SMEM_64>>>(
        y2h, y2l, w3h, b3, y3h, y3l, nullptr, D2_, D3_, D3_);
    // 7) out = y3 @ w4^T + b4         K=128, N=658, BN=64 -> 704 CTAs
    gemm_mma<32, false, true><<<dim3(B_ / 128, (T_ + 63) / 64), 128, SMEM_64>>>(
        y3h, y3l, w4h, b4, nullptr, nullptr, out, D3_, T_, T_);
}